// round 13
// baseline (speedup 1.0000x reference)
#include <cuda_runtime.h>
#include <cuda_bf16.h>
#include <mma.h>
#include <cstdint>

using namespace nvcuda;

// ---------------------------------------------------------------------------
// Windowed XCA attention, fp32. B=4, C=192, H=W=224, WS=7 -> nW=4096 windows.
//   W: wprep — weights -> bf16 hi/lo row-major copies
//   X: xprep — x -> bf16 hi/lo planar copies (g_xb)
//   A: QKV GEMM  WMMA bf16x3, CTA 192x128               -> g_qkv (no bias)
//   C: attention per (window,head), qkv bias folded; writes bf16 hi/lo
//      directly into g_xb (proj's B operand)
//   D: proj GEMM WMMA bf16x3, CTA 192x128 -> out;  E: +bias
// ---------------------------------------------------------------------------

#define BATCH 4
#define CH    192
#define IMG   224
#define HW    50176
#define HEADS 6
#define HC    32
#define NW    4096
#define OQ    576
#define NPIX  49
#define CSTR  50

#define GBM 192
#define GBN 128
#define GBK 32
#define ASTR 56     // a_s row stride (elements); 112B, conflict-free
#define BSTR 136    // b_s row stride (elements); 272B, conflict-free
#define A_STAGE (GBM * ASTR)            // 10752 elem
#define B_STAGE (GBK * BSTR)            // 4352 elem
#define GEMM_SMEM ((2 * A_STAGE + 2 * B_STAGE) * 2)   // 60416 B

__device__ float g_qkv [(size_t)BATCH * OQ * HW];                 // 462 MB
__device__ __nv_bfloat16 g_xb[(size_t)BATCH * 2 * CH * HW];       // 154 MB
__device__ __nv_bfloat16 g_wq[2 * OQ * CH];                       // 442 KB
__device__ __nv_bfloat16 g_wp[2 * CH * CH];                       // 147 KB

__device__ __forceinline__ uint32_t smem_u32(const void* p) {
    uint32_t a;
    asm("{ .reg .u64 t; cvta.to.shared.u64 t, %1; cvt.u32.u64 %0, t; }" : "=r"(a) : "l"(p));
    return a;
}
__device__ __forceinline__ void cp16s(uint32_t d, const void* s) {
    asm volatile("cp.async.cg.shared.global [%0], [%1], 16;" :: "r"(d), "l"(s));
}

// ---------------------------------------------------------------------------
// W: weights -> bf16 hi/lo (row-major)
// ---------------------------------------------------------------------------
__global__ __launch_bounds__(256) void wprep(const float* __restrict__ wq,
                                             const float* __restrict__ wp)
{
    const int i = blockIdx.x * 256 + threadIdx.x;
    const int NQ = OQ * CH, NP = CH * CH;
    if (i < NQ) {
        const float v = wq[i];
        const __nv_bfloat16 hi = __float2bfloat16(v);
        g_wq[i] = hi;
        g_wq[NQ + i] = __float2bfloat16(v - __bfloat162float(hi));
    } else if (i < NQ + NP) {
        const int j = i - NQ;
        const float v = wp[j];
        const __nv_bfloat16 hi = __float2bfloat16(v);
        g_wp[j] = hi;
        g_wp[NP + j] = __float2bfloat16(v - __bfloat162float(hi));
    }
}

// ---------------------------------------------------------------------------
// X: x [b][c][p] fp32 -> g_xb[b][split][c][p] bf16 (hi, lo)
// ---------------------------------------------------------------------------
__global__ __launch_bounds__(256) void xprep(const float* __restrict__ src)
{
    const size_t q = (size_t)blockIdx.x * 256 + threadIdx.x;   // quad index
    const size_t PER_B = (size_t)CH * HW / 4;
    if (q >= (size_t)BATCH * PER_B) return;
    const size_t b = q / PER_B, r = q % PER_B;

    const float4 v = ((const float4*)src)[q];
    __nv_bfloat16 h[4], l[4];
    const float vv[4] = {v.x, v.y, v.z, v.w};
#pragma unroll
    for (int i = 0; i < 4; ++i) {
        h[i] = __float2bfloat16(vv[i]);
        l[i] = __float2bfloat16(vv[i] - __bfloat162float(h[i]));
    }
    const size_t base = (size_t)b * 2 * CH * HW;
    *(unsigned long long*)(g_xb + base + r * 4) = *(const unsigned long long*)h;
    *(unsigned long long*)(g_xb + base + (size_t)CH * HW + r * 4) = *(const unsigned long long*)l;
}

// ---------------------------------------------------------------------------
// GEMM: out[b][o][p] = sum_c w[o][c] * act[b][c][p], WMMA bf16x3.
// CTA 192(M) x 128(N), 384 thr (12 warps, warp tile 32x64), K chunks of 32,
// 18 chunks = 3 split terms x 6, double-buffered cp.async, dynamic smem.
// ---------------------------------------------------------------------------
template<int MROWS, int MODE>
__global__ __launch_bounds__(384, 2)
void gemm_wmma(float* __restrict__ out_p)
{
    extern __shared__ __nv_bfloat16 dsm[];
    __nv_bfloat16* a_s = dsm;                  // [2][192*56]
    __nv_bfloat16* b_s = dsm + 2 * A_STAGE;    // [2][32*136]

    const int t  = threadIdx.x;
    const int n0 = blockIdx.x * GBN;
    const int m0 = blockIdx.y * GBM;
    const int b  = blockIdx.z;

    const __nv_bfloat16* Abase = (MODE == 0) ? g_wq : g_wp;       // [2][MROWS][CH]
    const __nv_bfloat16* Bbase = g_xb + (size_t)b * 2 * CH * HW;  // [2][CH][HW]
    float* outb = ((MODE == 0) ? (float*)g_qkv : out_p)
                  + ((size_t)b * MROWS + m0) * HW + n0;

    auto issue = [&](int j, int s) {
        const int term = j / 6, kc = j % 6;
        const int sa = (term == 2) ? 1 : 0;       // A lo only in term 2
        const int sb = (term == 1) ? 1 : 0;       // B lo only in term 1
        const __nv_bfloat16* As = Abase + ((size_t)sa * MROWS + m0) * CH + kc * GBK;
        const __nv_bfloat16* Bs = Bbase + ((size_t)sb * CH + kc * GBK) * HW + n0;
        __nv_bfloat16* as = a_s + s * A_STAGE;
        __nv_bfloat16* bs = b_s + s * B_STAGE;
#pragma unroll
        for (int u = t; u < 768; u += 384) {      // A: 192 rows x 4 x 16B
            const int r = u >> 2, c = (u & 3) * 8;
            cp16s(smem_u32(&as[r * ASTR + c]), As + (size_t)r * CH + c);
        }
        for (int u = t; u < 512; u += 384) {      // B: 32 rows x 16 x 16B
            const int r = u >> 4, c = (u & 15) * 8;
            cp16s(smem_u32(&bs[r * BSTR + c]), Bs + (size_t)r * HW + c);
        }
        asm volatile("cp.async.commit_group;");
    };

    const int w  = t >> 5;
    const int wm = w >> 1;     // 0..5
    const int wn = w & 1;      // 0..1

    wmma::fragment<wmma::accumulator, 16, 16, 16, float> acc[2][4];
#pragma unroll
    for (int mi = 0; mi < 2; ++mi)
#pragma unroll
        for (int ni = 0; ni < 4; ++ni) wmma::fill_fragment(acc[mi][ni], 0.f);

    issue(0, 0);
    for (int j = 0; j < 18; ++j) {
        if (j + 1 < 18) {
            issue(j + 1, (j + 1) & 1);
            asm volatile("cp.async.wait_group 1;");
        } else {
            asm volatile("cp.async.wait_group 0;");
        }
        __syncthreads();

        const int s = j & 1;
        const __nv_bfloat16* as = a_s + s * A_STAGE;
        const __nv_bfloat16* bs = b_s + s * B_STAGE;
#pragma unroll
        for (int kk = 0; kk < 2; ++kk) {
            wmma::fragment<wmma::matrix_a, 16, 16, 16, __nv_bfloat16, wmma::row_major> af[2];
            wmma::fragment<wmma::matrix_b, 16, 16, 16, __nv_bfloat16, wmma::row_major> bf[4];
#pragma unroll
            for (int mi = 0; mi < 2; ++mi)
                wmma::load_matrix_sync(af[mi], &as[(wm * 32 + mi * 16) * ASTR + kk * 16], ASTR);
#pragma unroll
            for (int ni = 0; ni < 4; ++ni)
                wmma::load_matrix_sync(bf[ni], &bs[(kk * 16) * BSTR + wn * 64 + ni * 16], BSTR);
#pragma unroll
            for (int mi = 0; mi < 2; ++mi)
#pragma unroll
                for (int ni = 0; ni < 4; ++ni)
                    wmma::mma_sync(acc[mi][ni], af[mi], bf[ni], acc[mi][ni]);
        }
        __syncthreads();
    }

#pragma unroll
    for (int mi = 0; mi < 2; ++mi)
#pragma unroll
        for (int ni = 0; ni < 4; ++ni)
            wmma::store_matrix_sync(outb + (size_t)(wm * 32 + mi * 16) * HW + wn * 64 + ni * 16,
                                    acc[mi][ni], HW, wmma::mem_row_major);
}

// ---------------------------------------------------------------------------
// E: proj bias add: out[b][o][p] += bias[o]
// ---------------------------------------------------------------------------
__global__ __launch_bounds__(256) void bias_add(float* __restrict__ out,
                                                const float* __restrict__ bp)
{
    const size_t q = (size_t)blockIdx.x * 256 + threadIdx.x;
    if (q >= (size_t)BATCH * CH * HW / 4) return;
    const int o = (int)((q * 4 / HW) % CH);
    const float bb = bp[o];
    float4 v = ((float4*)out)[q];
    v.x += bb; v.y += bb; v.z += bb; v.w += bb;
    ((float4*)out)[q] = v;
}

// ---------------------------------------------------------------------------
// C: attention per (window, head) — round-9 core, qkv bias folded into load,
// phase-5 output written as bf16 hi/lo directly into g_xb (proj B operand).
// ---------------------------------------------------------------------------
__global__ __launch_bounds__(192)
void attn_kernel(const float* __restrict__ b_qkv,
                 const float* __restrict__ w_dw,
                 const float* __restrict__ b_dw,
                 const float* __restrict__ temperature)
{
    __shared__ float q_s[HC * CSTR];
    __shared__ float k_s[HC * CSTR + 4];
    __shared__ float v_s[HC * CSTR];
    __shared__ float at [NPIX * CSTR];
    __shared__ float invq[NPIX], invk[NPIX];

    const int win = blockIdx.x;
    const int h   = blockIdx.y;
    const int t   = threadIdx.x;
    const int b  = win >> 10;
    const int wh = (win >> 5) & 31;
    const int ww = win & 31;

    // ---- phase 0: coalesced load + qkv bias ----
    {
        const size_t gbase = (size_t)b * OQ * HW + (size_t)(wh * 7) * IMG + ww * 7;
#pragma unroll
        for (int it = 0; it < 25; ++it) {
            const int u = t + it * 192;
            if (u < 96 * NPIX) {
                const int c = u / NPIX, p = u % NPIX;
                const int sel = c >> 5, cc = c & 31;
                const int ch = sel * CH + h * HC + cc;
                const float v = __ldg(&g_qkv[gbase + (size_t)ch * HW + (p / 7) * IMG + p % 7])
                                + __ldg(&b_qkv[ch]);
                float* dstp = (sel == 0) ? q_s : (sel == 1) ? k_s : v_s;
                dstp[cc * CSTR + p] = v;
            }
        }
    }
    __syncthreads();

    // ---- phase 1: dwconv 3x3 in place ----
    {
        const int c    = t >> 1;
        const int half = t & 1;
        const int sel  = c >> 5;
        const int cc   = c & 31;
        const int ch   = sel * CH + h * HC + cc;
        float* dstp = (sel == 0) ? q_s : (sel == 1) ? k_s : v_s;
        float* row0 = dstp + cc * CSTR;

        float w9[9];
#pragma unroll
        for (int k = 0; k < 9; ++k) w9[k] = w_dw[ch * 9 + k];
        const float bb = b_dw[ch];

        float in[5][7];
        const int r0 = half ? 3 : 0;
        const int nr = half ? 4 : 5;
        for (int r = 0; r < nr; ++r)
#pragma unroll
            for (int j = 0; j < 7; ++j) in[r][j] = row0[(r0 + r) * 7 + j];
        __syncthreads();

        if (!half) {
#pragma unroll
            for (int i = 0; i < 4; ++i) {
#pragma unroll
                for (int j = 0; j < 7; ++j) {
                    float s = bb;
#pragma unroll
                    for (int di = -1; di <= 1; ++di) {
                        const int ii = i + di;
                        if (ii < 0) continue;
#pragma unroll
                        for (int dj = -1; dj <= 1; ++dj) {
                            const int jj = j + dj;
                            if (jj >= 0 && jj < 7)
                                s += w9[(di + 1) * 3 + (dj + 1)] * in[ii][jj];
                        }
                    }
                    row0[i * 7 + j] = s;
                }
            }
        } else {
#pragma unroll
            for (int i = 4; i < 7; ++i) {
#pragma unroll
                for (int j = 0; j < 7; ++j) {
                    float s = bb;
#pragma unroll
                    for (int di = -1; di <= 1; ++di) {
                        const int ii = i + di;
                        if (ii > 6) continue;
#pragma unroll
                        for (int dj = -1; dj <= 1; ++dj) {
                            const int jj = j + dj;
                            if (jj >= 0 && jj < 7)
                                s += w9[(di + 1) * 3 + (dj + 1)] * in[ii - 3][jj];
                        }
                    }
                    row0[i * 7 + j] = s;
                }
            }
        }
    }
    __syncthreads();

    // ---- phase 2: inverse norms ----
    if (t < 2 * NPIX) {
        const int part = t / NPIX, p = t % NPIX;
        const float* s = part ? k_s : q_s;
        float acc = 0.f;
#pragma unroll
        for (int c = 0; c < HC; ++c) { const float v = s[c * CSTR + p]; acc += v * v; }
        const float nm = fmaxf(sqrtf(acc), 1e-12f);
        if (part == 0) invq[p] = temperature[h] / nm;
        else           invk[p] = 1.f / nm;
    }
    __syncthreads();

    // ---- phase 3: KtQ, 4n x 7m tile ----
    if (t < 91) {
        const int n0 = 4 * (t / 7);
        const int m0 = 7 * (t % 7);
        float a0[7], a1[7], a2[7], a3[7];
#pragma unroll
        for (int jm = 0; jm < 7; ++jm) { a0[jm] = a1[jm] = a2[jm] = a3[jm] = 0.f; }
#pragma unroll
        for (int c = 0; c < HC; ++c) {
            const float2 ka = *(const float2*)&k_s[c * CSTR + n0];
            const float2 kb = *(const float2*)&k_s[c * CSTR + n0 + 2];
#pragma unroll
            for (int jm = 0; jm < 7; ++jm) {
                const float qv = q_s[c * CSTR + m0 + jm];
                a0[jm] += ka.x * qv;
                a1[jm] += ka.y * qv;
                a2[jm] += kb.x * qv;
                a3[jm] += kb.y * qv;
            }
        }
        const float ik0 = invk[n0];
#pragma unroll
        for (int jm = 0; jm < 7; ++jm)
            at[n0 * CSTR + m0 + jm] = a0[jm] * ik0 * invq[m0 + jm];
        if (n0 + 1 < NPIX) {
            const float ik1 = invk[n0 + 1];
            const float ik2 = invk[n0 + 2];
            const float ik3 = invk[n0 + 3];
#pragma unroll
            for (int jm = 0; jm < 7; ++jm) {
                const float iq = invq[m0 + jm];
                at[(n0 + 1) * CSTR + m0 + jm] = a1[jm] * ik1 * iq;
                at[(n0 + 2) * CSTR + m0 + jm] = a2[jm] * ik2 * iq;
                at[(n0 + 3) * CSTR + m0 + jm] = a3[jm] * ik3 * iq;
            }
        }
    }
    __syncthreads();

    // ---- phase 4: softmax over n (2 threads/col + shfl) ----
    {
        const int m = (t < 98) ? (t >> 1) : 0;
        const int part = t & 1;
        float mx = -1e30f;
        for (int n = part; n < NPIX; n += 2) mx = fmaxf(mx, at[n * CSTR + m]);
        mx = fmaxf(mx, __shfl_xor_sync(0xffffffffu, mx, 1));
        float ev[25];
        float ssum = 0.f;
        int cnt = 0;
        for (int n = part; n < NPIX; n += 2) {
            const float e = __expf(at[n * CSTR + m] - mx);
            ev[cnt++] = e;
            ssum += e;
        }
        ssum += __shfl_xor_sync(0xffffffffu, ssum, 1);
        const float r = 1.f / ssum;
        __syncthreads();
        if (t < 98) {
            cnt = 0;
            for (int n = part; n < NPIX; n += 2) at[n * CSTR + m] = ev[cnt++] * r;
        }
    }
    __syncthreads();

    // ---- phase 5: V*attn, 2c x 7m tile; write bf16 hi/lo into g_xb ----
    if (t < 112) {
        const int c0 = 2 * (t / 7), mg = t % 7;
        const int m0 = 7 * mg;
        float a0[7], a1[7];
#pragma unroll
        for (int jm = 0; jm < 7; ++jm) { a0[jm] = 0.f; a1[jm] = 0.f; }
#pragma unroll 4
        for (int n = 0; n < 48; n += 2) {
            const float2 v0 = *(const float2*)&v_s[c0 * CSTR + n];
            const float2 v1 = *(const float2*)&v_s[(c0 + 1) * CSTR + n];
#pragma unroll
            for (int jm = 0; jm < 7; ++jm) {
                const float at0 = at[n * CSTR + m0 + jm];
                const float at1 = at[(n + 1) * CSTR + m0 + jm];
                a0[jm] += v0.x * at0 + v0.y * at1;
                a1[jm] += v1.x * at0 + v1.y * at1;
            }
        }
        const float v48_0 = v_s[c0 * CSTR + 48];
        const float v48_1 = v_s[(c0 + 1) * CSTR + 48];
#pragma unroll
        for (int jm = 0; jm < 7; ++jm) {
            const float at48 = at[48 * CSTR + m0 + jm];
            a0[jm] += v48_0 * at48;
            a1[jm] += v48_1 * at48;
        }

        const int pix = (wh * 7 + mg) * IMG + ww * 7;
        __nv_bfloat16* dh = g_xb + ((size_t)b * 2 * CH + (h * HC + c0)) * HW + pix;
        __nv_bfloat16* dl = dh + (size_t)CH * HW;
#pragma unroll
        for (int jm = 0; jm < 7; ++jm) {
            const __nv_bfloat16 hi = __float2bfloat16(a0[jm]);
            dh[jm] = hi;
            dl[jm] = __float2bfloat16(a0[jm] - __bfloat162float(hi));
        }
        dh += HW; dl += HW;
#pragma unroll
        for (int jm = 0; jm < 7; ++jm) {
            const __nv_bfloat16 hi = __float2bfloat16(a1[jm]);
            dh[jm] = hi;
            dl[jm] = __float2bfloat16(a1[jm] - __bfloat162float(hi));
        }
    }
}

// ---------------------------------------------------------------------------
extern "C" void kernel_launch(void* const* d_in, const int* in_sizes, int n_in,
                              void* d_out, int out_size)
{
    const float* x      = (const float*)d_in[0];
    const float* w_qkv  = (const float*)d_in[1];
    const float* b_qkv  = (const float*)d_in[2];
    const float* w_dw   = (const float*)d_in[3];
    const float* b_dw   = (const float*)d_in[4];
    const float* w_proj = (const float*)d_in[5];
    const float* b_proj = (const float*)d_in[6];
    const float* temp   = (const float*)d_in[7];
    float* out = (float*)d_out;

    cudaFuncSetAttribute(gemm_wmma<OQ, 0>,
                         cudaFuncAttributeMaxDynamicSharedMemorySize, GEMM_SMEM);
    cudaFuncSetAttribute(gemm_wmma<CH, 1>,
                         cudaFuncAttributeMaxDynamicSharedMemorySize, GEMM_SMEM);

    const int XQ = (int)(((size_t)BATCH * CH * HW / 4 + 255) / 256);

    // W: weights -> bf16 hi/lo
    wprep<<<(OQ * CH + CH * CH + 255) / 256, 256>>>(w_qkv, w_proj);
    // X: x -> bf16 hi/lo planar
    xprep<<<XQ, 256>>>(x);
    // A: QKV GEMM (WMMA bf16x3) -> g_qkv
    gemm_wmma<OQ, 0><<<dim3(HW / GBN, OQ / GBM, BATCH), 384, GEMM_SMEM>>>(nullptr);
    // C: attention (qkv bias folded) -> g_xb (bf16 hi/lo)
    attn_kernel<<<dim3(NW, HEADS), 192>>>(b_qkv, w_dw, b_dw, temp);
    // D: proj GEMM (WMMA bf16x3) -> out
    gemm_wmma<CH, 1><<<dim3(HW / GBN, CH / GBM, BATCH), 384, GEMM_SMEM>>>(out);
    // E: proj bias
    bias_add<<<XQ, 256>>>(out, b_proj);
}

// round 14
// speedup vs baseline: 1.3431x; 1.3431x over previous
#include <cuda_runtime.h>
#include <cuda_bf16.h>
#include <mma.h>
#include <cstdint>

using namespace nvcuda;

// ---------------------------------------------------------------------------
// Windowed XCA attention, fp32. B=4, C=192, H=W=224, WS=7 -> nW=4096 windows.
//   W: wprep — weights -> bf16 hi/lo row-major copies
//   X: xprep — activations -> bf16 hi/lo planar copies
//   A: QKV GEMM  WMMA bf16x3 + bias epilogue -> g_qkv
//   C: attention per (window,head)           -> g_attn
//   X2: xprep on g_attn
//   D: proj GEMM WMMA bf16x3 + bias epilogue -> out
// ---------------------------------------------------------------------------

#define BATCH 4
#define CH    192
#define IMG   224
#define HW    50176
#define HEADS 6
#define HC    32
#define NW    4096
#define OQ    576
#define NPIX  49
#define CSTR  50

#define GBM 96
#define GBN 128
#define GBK 32
#define ASTR 56     // a_s row stride (elements); 112B, conflict-free
#define BSTR 136    // b_s row stride (elements); 272B, conflict-free

__device__ float g_qkv [(size_t)BATCH * OQ * HW];                 // 462 MB
__device__ float g_attn[(size_t)BATCH * CH * HW];                 // 154 MB
__device__ __nv_bfloat16 g_xb[(size_t)BATCH * 2 * CH * HW];       // 154 MB
__device__ __nv_bfloat16 g_wq[2 * OQ * CH];                       // 442 KB
__device__ __nv_bfloat16 g_wp[2 * CH * CH];                       // 147 KB

__device__ __forceinline__ uint32_t smem_u32(const void* p) {
    uint32_t a;
    asm("{ .reg .u64 t; cvta.to.shared.u64 t, %1; cvt.u32.u64 %0, t; }" : "=r"(a) : "l"(p));
    return a;
}
__device__ __forceinline__ void cp16s(uint32_t d, const void* s) {
    asm volatile("cp.async.cg.shared.global [%0], [%1], 16;" :: "r"(d), "l"(s));
}

// ---------------------------------------------------------------------------
// W: weights -> bf16 hi/lo (row-major, same indexing as source)
// ---------------------------------------------------------------------------
__global__ __launch_bounds__(256) void wprep(const float* __restrict__ wq,
                                             const float* __restrict__ wp)
{
    const int i = blockIdx.x * 256 + threadIdx.x;
    const int NQ = OQ * CH, NP = CH * CH;
    if (i < NQ) {
        const float v = wq[i];
        const __nv_bfloat16 hi = __float2bfloat16(v);
        g_wq[i] = hi;
        g_wq[NQ + i] = __float2bfloat16(v - __bfloat162float(hi));
    } else if (i < NQ + NP) {
        const int j = i - NQ;
        const float v = wp[j];
        const __nv_bfloat16 hi = __float2bfloat16(v);
        g_wp[j] = hi;
        g_wp[NP + j] = __float2bfloat16(v - __bfloat162float(hi));
    }
}

// ---------------------------------------------------------------------------
// X: activations [b][c][p] fp32 -> g_xb[b][split][c][p] bf16 (hi, lo)
// ---------------------------------------------------------------------------
template<int SRC>
__global__ __launch_bounds__(256) void xprep(const float* __restrict__ src_p)
{
    const float* src = (SRC == 0) ? src_p : (const float*)g_attn;
    const size_t q = (size_t)blockIdx.x * 256 + threadIdx.x;   // quad index
    const size_t PER_B = (size_t)CH * HW / 4;
    if (q >= (size_t)BATCH * PER_B) return;
    const size_t b = q / PER_B, r = q % PER_B;

    const float4 v = ((const float4*)src)[q];
    __nv_bfloat16 h[4], l[4];
    const float vv[4] = {v.x, v.y, v.z, v.w};
#pragma unroll
    for (int i = 0; i < 4; ++i) {
        h[i] = __float2bfloat16(vv[i]);
        l[i] = __float2bfloat16(vv[i] - __bfloat162float(h[i]));
    }
    const size_t base = (size_t)b * 2 * CH * HW;
    *(unsigned long long*)(g_xb + base + r * 4) = *(const unsigned long long*)h;
    *(unsigned long long*)(g_xb + base + (size_t)CH * HW + r * 4) = *(const unsigned long long*)l;
}

// ---------------------------------------------------------------------------
// GEMM: out[b][o][p] = bias[o] + sum_c w[o][c] * act[b][c][p], WMMA bf16x3.
// CTA 96(M) x 128(N), 192 thr (6 warps, warp tile 32x64), K chunks of 32,
// 18 chunks = 3 split terms x 6, double-buffered cp.async.
// Bias folded via accumulator-layout fragment add in the epilogue.
// ---------------------------------------------------------------------------
template<int MROWS, int MODE>
__global__ __launch_bounds__(192, 2)
void gemm_wmma(const float* __restrict__ bias, float* __restrict__ out_p)
{
    __shared__ __nv_bfloat16 a_s[2][GBM * ASTR];   // 21504 B
    __shared__ __nv_bfloat16 b_s[2][GBK * BSTR];   // 17408 B
    __shared__ float bias_s[GBM][16];              // 6144 B

    const int t  = threadIdx.x;
    const int n0 = blockIdx.x * GBN;
    const int m0 = blockIdx.y * GBM;
    const int b  = blockIdx.z;

    const __nv_bfloat16* Abase = (MODE == 0) ? g_wq : g_wp;       // [2][MROWS][CH]
    const __nv_bfloat16* Bbase = g_xb + (size_t)b * 2 * CH * HW;  // [2][CH][HW]
    float* outb = ((MODE == 0) ? (float*)g_qkv : out_p)
                  + ((size_t)b * MROWS + m0) * HW + n0;

    // stage bias rows (replicated across 16 cols -> accumulator-layout tile)
    for (int u = t; u < GBM * 16; u += 192) {
        const int r = u >> 4;
        bias_s[r][u & 15] = bias[m0 + r];
    }

    auto issue = [&](int j, int s) {
        const int term = j / 6, kc = j % 6;
        const int sa = (term == 2) ? 1 : 0;       // A lo only in term 2
        const int sb = (term == 1) ? 1 : 0;       // B lo only in term 1
        const __nv_bfloat16* As = Abase + ((size_t)sa * MROWS + m0) * CH + kc * GBK;
        const __nv_bfloat16* Bs = Bbase + ((size_t)sb * CH + kc * GBK) * HW + n0;
#pragma unroll
        for (int u = t; u < 384; u += 192) {      // A: 96 rows x 4 x 16B
            const int r = u >> 2, c = (u & 3) * 8;
            cp16s(smem_u32(&a_s[s][r * ASTR + c]), As + (size_t)r * CH + c);
        }
        for (int u = t; u < 512; u += 192) {      // B: 32 rows x 16 x 16B
            const int r = u >> 4, c = (u & 15) * 8;
            cp16s(smem_u32(&b_s[s][r * BSTR + c]), Bs + (size_t)r * HW + c);
        }
        asm volatile("cp.async.commit_group;");
    };

    const int w  = t >> 5;
    const int wm = w >> 1;     // 0..2
    const int wn = w & 1;      // 0..1

    wmma::fragment<wmma::accumulator, 16, 16, 16, float> acc[2][4];
#pragma unroll
    for (int mi = 0; mi < 2; ++mi)
#pragma unroll
        for (int ni = 0; ni < 4; ++ni) wmma::fill_fragment(acc[mi][ni], 0.f);

    issue(0, 0);
    for (int j = 0; j < 18; ++j) {
        if (j + 1 < 18) {
            issue(j + 1, (j + 1) & 1);
            asm volatile("cp.async.wait_group 1;");
        } else {
            asm volatile("cp.async.wait_group 0;");
        }
        __syncthreads();

        const int s = j & 1;
#pragma unroll
        for (int kk = 0; kk < 2; ++kk) {
            wmma::fragment<wmma::matrix_a, 16, 16, 16, __nv_bfloat16, wmma::row_major> af[2];
            wmma::fragment<wmma::matrix_b, 16, 16, 16, __nv_bfloat16, wmma::row_major> bf[4];
#pragma unroll
            for (int mi = 0; mi < 2; ++mi)
                wmma::load_matrix_sync(af[mi], &a_s[s][(wm * 32 + mi * 16) * ASTR + kk * 16], ASTR);
#pragma unroll
            for (int ni = 0; ni < 4; ++ni)
                wmma::load_matrix_sync(bf[ni], &b_s[s][(kk * 16) * BSTR + wn * 64 + ni * 16], BSTR);
#pragma unroll
            for (int mi = 0; mi < 2; ++mi)
#pragma unroll
                for (int ni = 0; ni < 4; ++ni)
                    wmma::mma_sync(acc[mi][ni], af[mi], bf[ni], acc[mi][ni]);
        }
        __syncthreads();
    }

    // epilogue: add bias via accumulator-layout fragment, then store
#pragma unroll
    for (int mi = 0; mi < 2; ++mi) {
        wmma::fragment<wmma::accumulator, 16, 16, 16, float> bfr;
        wmma::load_matrix_sync(bfr, &bias_s[wm * 32 + mi * 16][0], 16, wmma::mem_row_major);
#pragma unroll
        for (int ni = 0; ni < 4; ++ni) {
#pragma unroll
            for (int e = 0; e < bfr.num_elements; ++e) acc[mi][ni].x[e] += bfr.x[e];
            wmma::store_matrix_sync(outb + (size_t)(wm * 32 + mi * 16) * HW + wn * 64 + ni * 16,
                                    acc[mi][ni], HW, wmma::mem_row_major);
        }
    }
}

// ---------------------------------------------------------------------------
// C: attention per (window, head) — round-9 frozen core.
// ---------------------------------------------------------------------------
__global__ __launch_bounds__(192)
void attn_kernel(const float* __restrict__ w_dw,
                 const float* __restrict__ b_dw,
                 const float* __restrict__ temperature)
{
    __shared__ float q_s[HC * CSTR];
    __shared__ float k_s[HC * CSTR + 4];
    __shared__ float v_s[HC * CSTR];
    __shared__ float at [NPIX * CSTR];
    __shared__ float invq[NPIX], invk[NPIX];

    const int win = blockIdx.x;
    const int h   = blockIdx.y;
    const int t   = threadIdx.x;
    const int b  = win >> 10;
    const int wh = (win >> 5) & 31;
    const int ww = win & 31;

    // ---- phase 0: coalesced load ----
    {
        const size_t gbase = (size_t)b * OQ * HW + (size_t)(wh * 7) * IMG + ww * 7;
#pragma unroll
        for (int it = 0; it < 25; ++it) {
            const int u = t + it * 192;
            if (u < 96 * NPIX) {
                const int c = u / NPIX, p = u % NPIX;
                const int sel = c >> 5, cc = c & 31;
                const int ch = sel * CH + h * HC + cc;
                const float v = __ldg(&g_qkv[gbase + (size_t)ch * HW + (p / 7) * IMG + p % 7]);
                float* dstp = (sel == 0) ? q_s : (sel == 1) ? k_s : v_s;
                dstp[cc * CSTR + p] = v;
            }
        }
    }
    __syncthreads();

    // ---- phase 1: dwconv 3x3 in place ----
    {
        const int c    = t >> 1;
        const int half = t & 1;
        const int sel  = c >> 5;
        const int cc   = c & 31;
        const int ch   = sel * CH + h * HC + cc;
        float* dstp = (sel == 0) ? q_s : (sel == 1) ? k_s : v_s;
        float* row0 = dstp + cc * CSTR;

        float w9[9];
#pragma unroll
        for (int k = 0; k < 9; ++k) w9[k] = w_dw[ch * 9 + k];
        const float bb = b_dw[ch];

        float in[5][7];
        const int r0 = half ? 3 : 0;
        const int nr = half ? 4 : 5;
        for (int r = 0; r < nr; ++r)
#pragma unroll
            for (int j = 0; j < 7; ++j) in[r][j] = row0[(r0 + r) * 7 + j];
        __syncthreads();

        if (!half) {
#pragma unroll
            for (int i = 0; i < 4; ++i) {
#pragma unroll
                for (int j = 0; j < 7; ++j) {
                    float s = bb;
#pragma unroll
                    for (int di = -1; di <= 1; ++di) {
                        const int ii = i + di;
                        if (ii < 0) continue;
#pragma unroll
                        for (int dj = -1; dj <= 1; ++dj) {
                            const int jj = j + dj;
                            if (jj >= 0 && jj < 7)
                                s += w9[(di + 1) * 3 + (dj + 1)] * in[ii][jj];
                        }
                    }
                    row0[i * 7 + j] = s;
                }
            }
        } else {
#pragma unroll
            for (int i = 4; i < 7; ++i) {
#pragma unroll
                for (int j = 0; j < 7; ++j) {
                    float s = bb;
#pragma unroll
                    for (int di = -1; di <= 1; ++di) {
                        const int ii = i + di;
                        if (ii > 6) continue;
#pragma unroll
                        for (int dj = -1; dj <= 1; ++dj) {
                            const int jj = j + dj;
                            if (jj >= 0 && jj < 7)
                                s += w9[(di + 1) * 3 + (dj + 1)] * in[ii - 3][jj];
                        }
                    }
                    row0[i * 7 + j] = s;
                }
            }
        }
    }
    __syncthreads();

    // ---- phase 2: inverse norms ----
    if (t < 2 * NPIX) {
        const int part = t / NPIX, p = t % NPIX;
        const float* s = part ? k_s : q_s;
        float acc = 0.f;
#pragma unroll
        for (int c = 0; c < HC; ++c) { const float v = s[c * CSTR + p]; acc += v * v; }
        const float nm = fmaxf(sqrtf(acc), 1e-12f);
        if (part == 0) invq[p] = temperature[h] / nm;
        else           invk[p] = 1.f / nm;
    }
    __syncthreads();

    // ---- phase 3: KtQ, 4n x 7m tile ----
    if (t < 91) {
        const int n0 = 4 * (t / 7);
        const int m0 = 7 * (t % 7);
        float a0[7], a1[7], a2[7], a3[7];
#pragma unroll
        for (int jm = 0; jm < 7; ++jm) { a0[jm] = a1[jm] = a2[jm] = a3[jm] = 0.f; }
#pragma unroll
        for (int c = 0; c < HC; ++c) {
            const float2 ka = *(const float2*)&k_s[c * CSTR + n0];
            const float2 kb = *(const float2*)&k_s[c * CSTR + n0 + 2];
#pragma unroll
            for (int jm = 0; jm < 7; ++jm) {
                const float qv = q_s[c * CSTR + m0 + jm];
                a0[jm] += ka.x * qv;
                a1[jm] += ka.y * qv;
                a2[jm] += kb.x * qv;
                a3[jm] += kb.y * qv;
            }
        }
        const float ik0 = invk[n0];
#pragma unroll
        for (int jm = 0; jm < 7; ++jm)
            at[n0 * CSTR + m0 + jm] = a0[jm] * ik0 * invq[m0 + jm];
        if (n0 + 1 < NPIX) {
            const float ik1 = invk[n0 + 1];
            const float ik2 = invk[n0 + 2];
            const float ik3 = invk[n0 + 3];
#pragma unroll
            for (int jm = 0; jm < 7; ++jm) {
                const float iq = invq[m0 + jm];
                at[(n0 + 1) * CSTR + m0 + jm] = a1[jm] * ik1 * iq;
                at[(n0 + 2) * CSTR + m0 + jm] = a2[jm] * ik2 * iq;
                at[(n0 + 3) * CSTR + m0 + jm] = a3[jm] * ik3 * iq;
            }
        }
    }
    __syncthreads();

    // ---- phase 4: softmax over n (2 threads/col + shfl) ----
    {
        const int m = (t < 98) ? (t >> 1) : 0;
        const int part = t & 1;
        float mx = -1e30f;
        for (int n = part; n < NPIX; n += 2) mx = fmaxf(mx, at[n * CSTR + m]);
        mx = fmaxf(mx, __shfl_xor_sync(0xffffffffu, mx, 1));
        float ev[25];
        float ssum = 0.f;
        int cnt = 0;
        for (int n = part; n < NPIX; n += 2) {
            const float e = __expf(at[n * CSTR + m] - mx);
            ev[cnt++] = e;
            ssum += e;
        }
        ssum += __shfl_xor_sync(0xffffffffu, ssum, 1);
        const float r = 1.f / ssum;
        __syncthreads();
        if (t < 98) {
            cnt = 0;
            for (int n = part; n < NPIX; n += 2) at[n * CSTR + m] = ev[cnt++] * r;
        }
    }
    __syncthreads();

    // ---- phase 5: V*attn, 2c x 7m tile ----
    if (t < 112) {
        const int c0 = 2 * (t / 7), mg = t % 7;
        const int m0 = 7 * mg;
        float a0[7], a1[7];
#pragma unroll
        for (int jm = 0; jm < 7; ++jm) { a0[jm] = 0.f; a1[jm] = 0.f; }
#pragma unroll 4
        for (int n = 0; n < 48; n += 2) {
            const float2 v0 = *(const float2*)&v_s[c0 * CSTR + n];
            const float2 v1 = *(const float2*)&v_s[(c0 + 1) * CSTR + n];
#pragma unroll
            for (int jm = 0; jm < 7; ++jm) {
                const float at0 = at[n * CSTR + m0 + jm];
                const float at1 = at[(n + 1) * CSTR + m0 + jm];
                a0[jm] += v0.x * at0 + v0.y * at1;
                a1[jm] += v1.x * at0 + v1.y * at1;
            }
        }
        const float v48_0 = v_s[c0 * CSTR + 48];
        const float v48_1 = v_s[(c0 + 1) * CSTR + 48];
#pragma unroll
        for (int jm = 0; jm < 7; ++jm) {
            const float at48 = at[48 * CSTR + m0 + jm];
            a0[jm] += v48_0 * at48;
            a1[jm] += v48_1 * at48;
        }

        float* dst = g_attn + (((size_t)(b * CH + h * HC + c0) * IMG) + wh * 7 + mg) * IMG + ww * 7;
#pragma unroll
        for (int jm = 0; jm < 7; ++jm) dst[jm] = a0[jm];
        dst += (size_t)IMG * IMG;
#pragma unroll
        for (int jm = 0; jm < 7; ++jm) dst[jm] = a1[jm];
    }
}

// ---------------------------------------------------------------------------
extern "C" void kernel_launch(void* const* d_in, const int* in_sizes, int n_in,
                              void* d_out, int out_size)
{
    const float* x      = (const float*)d_in[0];
    const float* w_qkv  = (const float*)d_in[1];
    const float* b_qkv  = (const float*)d_in[2];
    const float* w_dw   = (const float*)d_in[3];
    const float* b_dw   = (const float*)d_in[4];
    const float* w_proj = (const float*)d_in[5];
    const float* b_proj = (const float*)d_in[6];
    const float* temp   = (const float*)d_in[7];
    float* out = (float*)d_out;

    const int XQ = (int)(((size_t)BATCH * CH * HW / 4 + 255) / 256);

    // W: weights -> bf16 hi/lo
    wprep<<<(OQ * CH + CH * CH + 255) / 256, 256>>>(w_qkv, w_proj);
    // X: x -> bf16 hi/lo planar
    xprep<0><<<XQ, 256>>>(x);
    // A: QKV GEMM (WMMA bf16x3, bias folded) -> g_qkv
    gemm_wmma<OQ, 0><<<dim3(HW / GBN, OQ / GBM, BATCH), 192>>>(b_qkv, nullptr);
    // C: attention -> g_attn
    attn_kernel<<<dim3(NW, HEADS), 192>>>(w_dw, b_dw, temp);
    // X2: g_attn -> bf16 hi/lo planar
    xprep<1><<<XQ, 256>>>(nullptr);
    // D: proj GEMM (WMMA bf16x3, bias folded) -> out
    gemm_wmma<CH, 1><<<dim3(HW / GBN, CH / GBM, BATCH), 192>>>(b_proj, out);
}

// round 15
// speedup vs baseline: 1.4970x; 1.1146x over previous
#include <cuda_runtime.h>
#include <cuda_bf16.h>
#include <mma.h>
#include <cstdint>

using namespace nvcuda;

// ---------------------------------------------------------------------------
// Windowed XCA attention, fp32. B=4, C=192, H=W=224, WS=7 -> nW=4096 windows.
//   W: wprep — weights -> bf16 hi/lo row-major copies
//   X: xprep — activations -> bf16 hi/lo planar copies
//   A: QKV GEMM  WMMA bf16x3 (fused 3-term K-chunks) + bias -> g_qkv
//   C: attention per (window,head)                          -> g_attn
//   X2: xprep on g_attn
//   D: proj GEMM WMMA bf16x3 + bias                         -> out
// ---------------------------------------------------------------------------

#define BATCH 4
#define CH    192
#define IMG   224
#define HW    50176
#define HEADS 6
#define HC    32
#define NW    4096
#define OQ    576
#define NPIX  49
#define CSTR  50

#define GBM 96
#define GBN 128
#define GBK 32
#define ASTR 56     // a_s row stride (elements); 112B, conflict-free
#define BSTR 136    // b_s row stride (elements); 272B, conflict-free
#define A_STAGE (GBM * ASTR)                         // 5376 elem
#define B_STAGE (GBK * BSTR)                         // 4352 elem
#define GEMM_SMEM ((4 * A_STAGE + 4 * B_STAGE) * 2)  // 77824 B dynamic

__device__ float g_qkv [(size_t)BATCH * OQ * HW];                 // 462 MB
__device__ float g_attn[(size_t)BATCH * CH * HW];                 // 154 MB
__device__ __nv_bfloat16 g_xb[(size_t)BATCH * 2 * CH * HW];       // 154 MB
__device__ __nv_bfloat16 g_wq[2 * OQ * CH];                       // 442 KB
__device__ __nv_bfloat16 g_wp[2 * CH * CH];                       // 147 KB

__device__ __forceinline__ uint32_t smem_u32(const void* p) {
    uint32_t a;
    asm("{ .reg .u64 t; cvta.to.shared.u64 t, %1; cvt.u32.u64 %0, t; }" : "=r"(a) : "l"(p));
    return a;
}
__device__ __forceinline__ void cp16s(uint32_t d, const void* s) {
    asm volatile("cp.async.cg.shared.global [%0], [%1], 16;" :: "r"(d), "l"(s));
}

// ---------------------------------------------------------------------------
// W: weights -> bf16 hi/lo (row-major, same indexing as source)
// ---------------------------------------------------------------------------
__global__ __launch_bounds__(256) void wprep(const float* __restrict__ wq,
                                             const float* __restrict__ wp)
{
    const int i = blockIdx.x * 256 + threadIdx.x;
    const int NQ = OQ * CH, NP = CH * CH;
    if (i < NQ) {
        const float v = wq[i];
        const __nv_bfloat16 hi = __float2bfloat16(v);
        g_wq[i] = hi;
        g_wq[NQ + i] = __float2bfloat16(v - __bfloat162float(hi));
    } else if (i < NQ + NP) {
        const int j = i - NQ;
        const float v = wp[j];
        const __nv_bfloat16 hi = __float2bfloat16(v);
        g_wp[j] = hi;
        g_wp[NP + j] = __float2bfloat16(v - __bfloat162float(hi));
    }
}

// ---------------------------------------------------------------------------
// X: activations [b][c][p] fp32 -> g_xb[b][split][c][p] bf16 (hi, lo)
// ---------------------------------------------------------------------------
template<int SRC>
__global__ __launch_bounds__(256) void xprep(const float* __restrict__ src_p)
{
    const float* src = (SRC == 0) ? src_p : (const float*)g_attn;
    const size_t q = (size_t)blockIdx.x * 256 + threadIdx.x;   // quad index
    const size_t PER_B = (size_t)CH * HW / 4;
    if (q >= (size_t)BATCH * PER_B) return;
    const size_t b = q / PER_B, r = q % PER_B;

    const float4 v = ((const float4*)src)[q];
    __nv_bfloat16 h[4], l[4];
    const float vv[4] = {v.x, v.y, v.z, v.w};
#pragma unroll
    for (int i = 0; i < 4; ++i) {
        h[i] = __float2bfloat16(vv[i]);
        l[i] = __float2bfloat16(vv[i] - __bfloat162float(h[i]));
    }
    const size_t base = (size_t)b * 2 * CH * HW;
    *(unsigned long long*)(g_xb + base + r * 4) = *(const unsigned long long*)h;
    *(unsigned long long*)(g_xb + base + (size_t)CH * HW + r * 4) = *(const unsigned long long*)l;
}

// ---------------------------------------------------------------------------
// GEMM: out[b][o][p] = bias[o] + sum_c w[o][c] * act[b][c][p], WMMA bf16x3.
// CTA 96(M) x 128(N), 192 thr (6 warps, warp tile 32x64).
// 6 K-chunks of 32; each chunk stages A-hi/A-lo/B-hi/B-lo once and computes
// Ahi*Bhi + Ahi*Blo + Alo*Bhi. Double-buffered cp.async, dynamic smem.
// Bias folded via accumulator-layout fragment add in the epilogue.
// ---------------------------------------------------------------------------
template<int MROWS, int MODE>
__global__ __launch_bounds__(192, 2)
void gemm_wmma(const float* __restrict__ bias, float* __restrict__ out_p)
{
    extern __shared__ __nv_bfloat16 dsm[];
    // layout: [buf(2)][split(2)] A planes, then [buf(2)][split(2)] B planes
    __nv_bfloat16* a_pl = dsm;                       // 4 * A_STAGE
    __nv_bfloat16* b_pl = dsm + 4 * A_STAGE;         // 4 * B_STAGE
    __shared__ float bias_s[GBM][16];                // 6144 B static

    const int t  = threadIdx.x;
    const int n0 = blockIdx.x * GBN;
    const int m0 = blockIdx.y * GBM;
    const int b  = blockIdx.z;

    const __nv_bfloat16* Abase = (MODE == 0) ? g_wq : g_wp;       // [2][MROWS][CH]
    const __nv_bfloat16* Bbase = g_xb + (size_t)b * 2 * CH * HW;  // [2][CH][HW]
    float* outb = ((MODE == 0) ? (float*)g_qkv : out_p)
                  + ((size_t)b * MROWS + m0) * HW + n0;

    // stage bias rows (replicated across 16 cols -> accumulator-layout tile)
    for (int u = t; u < GBM * 16; u += 192) {
        const int r = u >> 4;
        bias_s[r][u & 15] = bias[m0 + r];
    }

    auto issue = [&](int kc, int s) {
#pragma unroll
        for (int sp = 0; sp < 2; ++sp) {
            const __nv_bfloat16* As = Abase + ((size_t)sp * MROWS + m0) * CH + kc * GBK;
            const __nv_bfloat16* Bs = Bbase + ((size_t)sp * CH + kc * GBK) * HW + n0;
            __nv_bfloat16* ad = a_pl + (s * 2 + sp) * A_STAGE;
            __nv_bfloat16* bd = b_pl + (s * 2 + sp) * B_STAGE;
#pragma unroll
            for (int u = t; u < 384; u += 192) {      // A: 96 rows x 4 x 16B
                const int r = u >> 2, c = (u & 3) * 8;
                cp16s(smem_u32(&ad[r * ASTR + c]), As + (size_t)r * CH + c);
            }
            for (int u = t; u < 512; u += 192) {      // B: 32 rows x 16 x 16B
                const int r = u >> 4, c = (u & 15) * 8;
                cp16s(smem_u32(&bd[r * BSTR + c]), Bs + (size_t)r * HW + c);
            }
        }
        asm volatile("cp.async.commit_group;");
    };

    const int w  = t >> 5;
    const int wm = w >> 1;     // 0..2
    const int wn = w & 1;      // 0..1

    wmma::fragment<wmma::accumulator, 16, 16, 16, float> acc[2][4];
#pragma unroll
    for (int mi = 0; mi < 2; ++mi)
#pragma unroll
        for (int ni = 0; ni < 4; ++ni) wmma::fill_fragment(acc[mi][ni], 0.f);

    issue(0, 0);
    for (int j = 0; j < 6; ++j) {
        if (j + 1 < 6) {
            issue(j + 1, (j + 1) & 1);
            asm volatile("cp.async.wait_group 1;");
        } else {
            asm volatile("cp.async.wait_group 0;");
        }
        __syncthreads();

        const int s = j & 1;
        const __nv_bfloat16* ah = a_pl + (s * 2 + 0) * A_STAGE;
        const __nv_bfloat16* al = a_pl + (s * 2 + 1) * A_STAGE;
        const __nv_bfloat16* bh = b_pl + (s * 2 + 0) * B_STAGE;
        const __nv_bfloat16* bl = b_pl + (s * 2 + 1) * B_STAGE;
#pragma unroll
        for (int kk = 0; kk < 2; ++kk) {
            wmma::fragment<wmma::matrix_a, 16, 16, 16, __nv_bfloat16, wmma::row_major> afh[2], afl[2];
            wmma::fragment<wmma::matrix_b, 16, 16, 16, __nv_bfloat16, wmma::row_major> bfh[4], bfl[4];
#pragma unroll
            for (int mi = 0; mi < 2; ++mi) {
                wmma::load_matrix_sync(afh[mi], &ah[(wm * 32 + mi * 16) * ASTR + kk * 16], ASTR);
                wmma::load_matrix_sync(afl[mi], &al[(wm * 32 + mi * 16) * ASTR + kk * 16], ASTR);
            }
#pragma unroll
            for (int ni = 0; ni < 4; ++ni) {
                wmma::load_matrix_sync(bfh[ni], &bh[(kk * 16) * BSTR + wn * 64 + ni * 16], BSTR);
                wmma::load_matrix_sync(bfl[ni], &bl[(kk * 16) * BSTR + wn * 64 + ni * 16], BSTR);
            }
#pragma unroll
            for (int mi = 0; mi < 2; ++mi)
#pragma unroll
                for (int ni = 0; ni < 4; ++ni) {
                    wmma::mma_sync(acc[mi][ni], afh[mi], bfh[ni], acc[mi][ni]);
                    wmma::mma_sync(acc[mi][ni], afh[mi], bfl[ni], acc[mi][ni]);
                    wmma::mma_sync(acc[mi][ni], afl[mi], bfh[ni], acc[mi][ni]);
                }
        }
        __syncthreads();
    }

    // epilogue: add bias via accumulator-layout fragment, then store
#pragma unroll
    for (int mi = 0; mi < 2; ++mi) {
        wmma::fragment<wmma::accumulator, 16, 16, 16, float> bfr;
        wmma::load_matrix_sync(bfr, &bias_s[wm * 32 + mi * 16][0], 16, wmma::mem_row_major);
#pragma unroll
        for (int ni = 0; ni < 4; ++ni) {
#pragma unroll
            for (int e = 0; e < bfr.num_elements; ++e) acc[mi][ni].x[e] += bfr.x[e];
            wmma::store_matrix_sync(outb + (size_t)(wm * 32 + mi * 16) * HW + wn * 64 + ni * 16,
                                    acc[mi][ni], HW, wmma::mem_row_major);
        }
    }
}

// ---------------------------------------------------------------------------
// C: attention per (window, head) — round-9 frozen core.
// ---------------------------------------------------------------------------
__global__ __launch_bounds__(192)
void attn_kernel(const float* __restrict__ w_dw,
                 const float* __restrict__ b_dw,
                 const float* __restrict__ temperature)
{
    __shared__ float q_s[HC * CSTR];
    __shared__ float k_s[HC * CSTR + 4];
    __shared__ float v_s[HC * CSTR];
    __shared__ float at [NPIX * CSTR];
    __shared__ float invq[NPIX], invk[NPIX];

    const int win = blockIdx.x;
    const int h   = blockIdx.y;
    const int t   = threadIdx.x;
    const int b  = win >> 10;
    const int wh = (win >> 5) & 31;
    const int ww = win & 31;

    // ---- phase 0: coalesced load ----
    {
        const size_t gbase = (size_t)b * OQ * HW + (size_t)(wh * 7) * IMG + ww * 7;
#pragma unroll
        for (int it = 0; it < 25; ++it) {
            const int u = t + it * 192;
            if (u < 96 * NPIX) {
                const int c = u / NPIX, p = u % NPIX;
                const int sel = c >> 5, cc = c & 31;
                const int ch = sel * CH + h * HC + cc;
                const float v = __ldg(&g_qkv[gbase + (size_t)ch * HW + (p / 7) * IMG + p % 7]);
                float* dstp = (sel == 0) ? q_s : (sel == 1) ? k_s : v_s;
                dstp[cc * CSTR + p] = v;
            }
        }
    }
    __syncthreads();

    // ---- phase 1: dwconv 3x3 in place ----
    {
        const int c    = t >> 1;
        const int half = t & 1;
        const int sel  = c >> 5;
        const int cc   = c & 31;
        const int ch   = sel * CH + h * HC + cc;
        float* dstp = (sel == 0) ? q_s : (sel == 1) ? k_s : v_s;
        float* row0 = dstp + cc * CSTR;

        float w9[9];
#pragma unroll
        for (int k = 0; k < 9; ++k) w9[k] = w_dw[ch * 9 + k];
        const float bb = b_dw[ch];

        float in[5][7];
        const int r0 = half ? 3 : 0;
        const int nr = half ? 4 : 5;
        for (int r = 0; r < nr; ++r)
#pragma unroll
            for (int j = 0; j < 7; ++j) in[r][j] = row0[(r0 + r) * 7 + j];
        __syncthreads();

        if (!half) {
#pragma unroll
            for (int i = 0; i < 4; ++i) {
#pragma unroll
                for (int j = 0; j < 7; ++j) {
                    float s = bb;
#pragma unroll
                    for (int di = -1; di <= 1; ++di) {
                        const int ii = i + di;
                        if (ii < 0) continue;
#pragma unroll
                        for (int dj = -1; dj <= 1; ++dj) {
                            const int jj = j + dj;
                            if (jj >= 0 && jj < 7)
                                s += w9[(di + 1) * 3 + (dj + 1)] * in[ii][jj];
                        }
                    }
                    row0[i * 7 + j] = s;
                }
            }
        } else {
#pragma unroll
            for (int i = 4; i < 7; ++i) {
#pragma unroll
                for (int j = 0; j < 7; ++j) {
                    float s = bb;
#pragma unroll
                    for (int di = -1; di <= 1; ++di) {
                        const int ii = i + di;
                        if (ii > 6) continue;
#pragma unroll
                        for (int dj = -1; dj <= 1; ++dj) {
                            const int jj = j + dj;
                            if (jj >= 0 && jj < 7)
                                s += w9[(di + 1) * 3 + (dj + 1)] * in[ii - 3][jj];
                        }
                    }
                    row0[i * 7 + j] = s;
                }
            }
        }
    }
    __syncthreads();

    // ---- phase 2: inverse norms ----
    if (t < 2 * NPIX) {
        const int part = t / NPIX, p = t % NPIX;
        const float* s = part ? k_s : q_s;
        float acc = 0.f;
#pragma unroll
        for (int c = 0; c < HC; ++c) { const float v = s[c * CSTR + p]; acc += v * v; }
        const float nm = fmaxf(sqrtf(acc), 1e-12f);
        if (part == 0) invq[p] = temperature[h] / nm;
        else           invk[p] = 1.f / nm;
    }
    __syncthreads();

    // ---- phase 3: KtQ, 4n x 7m tile ----
    if (t < 91) {
        const int n0 = 4 * (t / 7);
        const int m0 = 7 * (t % 7);
        float a0[7], a1[7], a2[7], a3[7];
#pragma unroll
        for (int jm = 0; jm < 7; ++jm) { a0[jm] = a1[jm] = a2[jm] = a3[jm] = 0.f; }
#pragma unroll
        for (int c = 0; c < HC; ++c) {
            const float2 ka = *(const float2*)&k_s[c * CSTR + n0];
            const float2 kb = *(const float2*)&k_s[c * CSTR + n0 + 2];
#pragma unroll
            for (int jm = 0; jm < 7; ++jm) {
                const float qv = q_s[c * CSTR + m0 + jm];
                a0[jm] += ka.x * qv;
                a1[jm] += ka.y * qv;
                a2[jm] += kb.x * qv;
                a3[jm] += kb.y * qv;
            }
        }
        const float ik0 = invk[n0];
#pragma unroll
        for (int jm = 0; jm < 7; ++jm)
            at[n0 * CSTR + m0 + jm] = a0[jm] * ik0 * invq[m0 + jm];
        if (n0 + 1 < NPIX) {
            const float ik1 = invk[n0 + 1];
            const float ik2 = invk[n0 + 2];
            const float ik3 = invk[n0 + 3];
#pragma unroll
            for (int jm = 0; jm < 7; ++jm) {
                const float iq = invq[m0 + jm];
                at[(n0 + 1) * CSTR + m0 + jm] = a1[jm] * ik1 * iq;
                at[(n0 + 2) * CSTR + m0 + jm] = a2[jm] * ik2 * iq;
                at[(n0 + 3) * CSTR + m0 + jm] = a3[jm] * ik3 * iq;
            }
        }
    }
    __syncthreads();

    // ---- phase 4: softmax over n (2 threads/col + shfl) ----
    {
        const int m = (t < 98) ? (t >> 1) : 0;
        const int part = t & 1;
        float mx = -1e30f;
        for (int n = part; n < NPIX; n += 2) mx = fmaxf(mx, at[n * CSTR + m]);
        mx = fmaxf(mx, __shfl_xor_sync(0xffffffffu, mx, 1));
        float ev[25];
        float ssum = 0.f;
        int cnt = 0;
        for (int n = part; n < NPIX; n += 2) {
            const float e = __expf(at[n * CSTR + m] - mx);
            ev[cnt++] = e;
            ssum += e;
        }
        ssum += __shfl_xor_sync(0xffffffffu, ssum, 1);
        const float r = 1.f / ssum;
        __syncthreads();
        if (t < 98) {
            cnt = 0;
            for (int n = part; n < NPIX; n += 2) at[n * CSTR + m] = ev[cnt++] * r;
        }
    }
    __syncthreads();

    // ---- phase 5: V*attn, 2c x 7m tile ----
    if (t < 112) {
        const int c0 = 2 * (t / 7), mg = t % 7;
        const int m0 = 7 * mg;
        float a0[7], a1[7];
#pragma unroll
        for (int jm = 0; jm < 7; ++jm) { a0[jm] = 0.f; a1[jm] = 0.f; }
#pragma unroll 4
        for (int n = 0; n < 48; n += 2) {
            const float2 v0 = *(const float2*)&v_s[c0 * CSTR + n];
            const float2 v1 = *(const float2*)&v_s[(c0 + 1) * CSTR + n];
#pragma unroll
            for (int jm = 0; jm < 7; ++jm) {
                const float at0 = at[n * CSTR + m0 + jm];
                const float at1 = at[(n + 1) * CSTR + m0 + jm];
                a0[jm] += v0.x * at0 + v0.y * at1;
                a1[jm] += v1.x * at0 + v1.y * at1;
            }
        }
        const float v48_0 = v_s[c0 * CSTR + 48];
        const float v48_1 = v_s[(c0 + 1) * CSTR + 48];
#pragma unroll
        for (int jm = 0; jm < 7; ++jm) {
            const float at48 = at[48 * CSTR + m0 + jm];
            a0[jm] += v48_0 * at48;
            a1[jm] += v48_1 * at48;
        }

        float* dst = g_attn + (((size_t)(b * CH + h * HC + c0) * IMG) + wh * 7 + mg) * IMG + ww * 7;
#pragma unroll
        for (int jm = 0; jm < 7; ++jm) dst[jm] = a0[jm];
        dst += (size_t)IMG * IMG;
#pragma unroll
        for (int jm = 0; jm < 7; ++jm) dst[jm] = a1[jm];
    }
}

// ---------------------------------------------------------------------------
extern "C" void kernel_launch(void* const* d_in, const int* in_sizes, int n_in,
                              void* d_out, int out_size)
{
    const float* x      = (const float*)d_in[0];
    const float* w_qkv  = (const float*)d_in[1];
    const float* b_qkv  = (const float*)d_in[2];
    const float* w_dw   = (const float*)d_in[3];
    const float* b_dw   = (const float*)d_in[4];
    const float* w_proj = (const float*)d_in[5];
    const float* b_proj = (const float*)d_in[6];
    const float* temp   = (const float*)d_in[7];
    float* out = (float*)d_out;

    cudaFuncSetAttribute(gemm_wmma<OQ, 0>,
                         cudaFuncAttributeMaxDynamicSharedMemorySize, GEMM_SMEM);
    cudaFuncSetAttribute(gemm_wmma<CH, 1>,
                         cudaFuncAttributeMaxDynamicSharedMemorySize, GEMM_SMEM);

    const int XQ = (int)(((size_t)BATCH * CH * HW / 4 + 255) / 256);

    // W: weights -> bf16 hi/lo
    wprep<<<(OQ * CH + CH * CH + 255) / 256, 256>>>(w_qkv, w_proj);
    // X: x -> bf16 hi/lo planar
    xprep<0><<<XQ, 256>>>(x);
    // A: QKV GEMM (WMMA bf16x3 fused chunks, bias folded) -> g_qkv
    gemm_wmma<OQ, 0><<<dim3(HW / GBN, OQ / GBM, BATCH), 192, GEMM_SMEM>>>(b_qkv, nullptr);
    // C: attention -> g_attn
    attn_kernel<<<dim3(NW, HEADS), 192>>>(w_dw, b_dw, temp);
    // X2: g_attn -> bf16 hi/lo planar
    xprep<1><<<XQ, 256>>>(nullptr);
    // D: proj GEMM (WMMA bf16x3 fused chunks, bias folded) -> out
    gemm_wmma<CH, 1><<<dim3(HW / GBN, CH / GBM, BATCH), 192, GEMM_SMEM>>>(b_proj, out);
}